// round 16
// baseline (speedup 1.0000x reference)
#include <cuda_runtime.h>
#include <cuda_bf16.h>

// Problem constants
#define TT   64
#define WW   88
#define HPc  48
#define CIN  53
#define HLc  12
#define G4   48
#define NHh  4
#define HDd  6
#define NUc  24
#define KK   25
#define NPX  (TT*WW)   // 5632
#define PITCH 26
#define UROWS 28
#define RPROWS 28

// Scratch buffers (device globals)
__device__ float g_q0[NPX*NUc];
__device__ float g_k0[NPX*NUc];
__device__ float g_v0[NPX*NUc];
__device__ float g_q1[NPX*NUc];
__device__ float g_k1[NPX*NUc];
__device__ float g_v1[NPX*NUc];

#define QSCALE 0.4082482904638631f

__device__ __forceinline__ float sigf(float x) {
    return __fdividef(1.0f, 1.0f + __expf(-x));
}
__device__ __forceinline__ float tanh_fast(float x) {
    return fmaf(2.0f, __fdividef(1.0f, 1.0f + __expf(-2.0f*x)), -1.0f);
}

// Polynomial exp on the FMA pipe (no MUFU). rel err ~1e-7 on |x|<~60.
__device__ __forceinline__ float exp_fma(float x) {
    float y  = x * 1.4426950408889634f;           // log2(e)
    float fn = y + 12582912.0f;                   // round-to-nearest (2^23+2^22)
    int   n  = __float_as_int(fn) - 0x4B400000;   // integer part
    float f  = y - (fn - 12582912.0f);            // frac in [-0.5, 0.5]
    // 2^f, degree-5 minimax-ish (Taylor in ln2*f)
    float p = 1.3388581208e-3f;
    p = fmaf(p, f, 9.6184236460e-3f);
    p = fmaf(p, f, 5.5502490997e-2f);
    p = fmaf(p, f, 2.4022644851e-1f);
    p = fmaf(p, f, 6.9314720304e-1f);
    p = fmaf(p, f, 1.0f);
    return __int_as_float(__float_as_int(p) + (n << 23));
}

// ---------------------------------------------------------------------------
// Fused LSTM + QKV(layer1). Block per sequence (w), 768 threads. (R14 exact)
// ---------------------------------------------------------------------------
__global__ void __launch_bounds__(768)
lstm_kernel(const float* __restrict__ features,
            const int*   __restrict__ condition,
            const float* __restrict__ mask,
            const float* __restrict__ emb,
            const float* __restrict__ wih0, const float* __restrict__ whh0,
            const float* __restrict__ bih0, const float* __restrict__ bhh0,
            const float* __restrict__ wih1, const float* __restrict__ whh1,
            const float* __restrict__ bih1, const float* __restrict__ bhh1,
            const float* __restrict__ qkv_w,
            const float* __restrict__ qkv_b)
{
    const int w   = blockIdx.x;
    const int tid = threadIdx.x;

    __shared__ float xs  [TT][CIN];
    __shared__ float pre [TT][96];
    __shared__ float hbuf[TT][2*HLc];
    __shared__ float w0sh [96*CIN];
    __shared__ float wh0sh[96*HLc];
    __shared__ float w1sh [96*2*HLc];
    __shared__ float wh1sh[96*HLc];
    __shared__ float wqsh [72*NUc];
    __shared__ float b0sh[96], b1sh[96], bqsh[72];

    for (int idx = tid; idx < TT*CIN; idx += 768) {
        int t = idx / CIN, c = idx % CIN;
        float val;
        if (c < HPc)            val = features[(t*HPc + c)*WW + w];
        else if (c < HPc + 4)   val = emb[condition[t*WW + w]*4 + (c - HPc)];
        else                    val = mask[t*WW + w];
        xs[t][c] = val;
    }
    for (int x = tid; x < 96*CIN/4;   x += 768)
        ((float4*)w0sh)[x]  = ((const float4*)wih0)[x];
    for (int x = tid; x < 96*HLc/4;   x += 768)
        ((float4*)wh0sh)[x] = ((const float4*)whh0)[x];
    for (int x = tid; x < 96*2*HLc/4; x += 768)
        ((float4*)w1sh)[x]  = ((const float4*)wih1)[x];
    for (int x = tid; x < 96*HLc/4;   x += 768)
        ((float4*)wh1sh)[x] = ((const float4*)whh1)[x];
    for (int x = tid; x < 72*NUc/4;   x += 768)
        ((float4*)wqsh)[x]  = ((const float4*)qkv_w)[x];
    if (tid < 96) b0sh[tid] = bih0[tid] + bhh0[tid];
    if (tid < 96) b1sh[tid] = bih1[tid] + bhh1[tid];
    if (tid < 72) bqsh[tid] = qkv_b[tid];
    __syncthreads();

    {
        const int gate = tid % 96;
        const int tq   = tid / 96;
        float wr[CIN];
        #pragma unroll
        for (int c = 0; c < CIN; c++) wr[c] = w0sh[gate*CIN + c];
        const float b = b0sh[gate];
        for (int t = tq*8; t < tq*8 + 8; t++) {
            float a0 = b, a1 = 0.f, a2 = 0.f, a3 = 0.f;
            #pragma unroll
            for (int c = 0; c < 52; c += 4) {
                a0 = fmaf(xs[t][c+0], wr[c+0], a0);
                a1 = fmaf(xs[t][c+1], wr[c+1], a1);
                a2 = fmaf(xs[t][c+2], wr[c+2], a2);
                a3 = fmaf(xs[t][c+3], wr[c+3], a3);
            }
            a0 = fmaf(xs[t][52], wr[52], a0);
            pre[t][gate] = (a0 + a1) + (a2 + a3);
        }
    }
    __syncthreads();

    if (tid < 64) {
        const int dir = tid >> 5, u = tid & 31;
        float wi[HLc], wf[HLc], wg[HLc], wo[HLc];
        if (u < HLc) {
            #pragma unroll
            for (int c = 0; c < HLc; c++) {
                wi[c] = wh0sh[(dir*G4      + u)*HLc + c];
                wf[c] = wh0sh[(dir*G4 + 12 + u)*HLc + c];
                wg[c] = wh0sh[(dir*G4 + 24 + u)*HLc + c];
                wo[c] = wh0sh[(dir*G4 + 36 + u)*HLc + c];
            }
        } else {
            #pragma unroll
            for (int c = 0; c < HLc; c++) { wi[c]=wf[c]=wg[c]=wo[c]=0.f; }
        }
        float h = 0.f, cs = 0.f;
        for (int s = 0; s < TT; s++) {
            const int t = dir ? (TT - 1 - s) : s;
            float gi, gf, gg, go;
            if (u < HLc) {
                gi = pre[t][dir*G4      + u];
                gf = pre[t][dir*G4 + 12 + u];
                gg = pre[t][dir*G4 + 24 + u];
                go = pre[t][dir*G4 + 36 + u];
            } else { gi = gf = gg = go = 0.f; }
            #pragma unroll
            for (int c = 0; c < HLc; c++) {
                float hc = __shfl_sync(0xffffffffu, h, c);
                gi = fmaf(hc, wi[c], gi);
                gf = fmaf(hc, wf[c], gf);
                gg = fmaf(hc, wg[c], gg);
                go = fmaf(hc, wo[c], go);
            }
            cs = sigf(gf)*cs + sigf(gi)*tanh_fast(gg);
            h  = sigf(go)*tanh_fast(cs);
            if (u < HLc) hbuf[t][dir*HLc + u] = h;
        }
    }
    __syncthreads();

    {
        const int gate = tid % 96;
        const int tq   = tid / 96;
        float wr[2*HLc];
        #pragma unroll
        for (int c = 0; c < 2*HLc; c++) wr[c] = w1sh[gate*2*HLc + c];
        const float b = b1sh[gate];
        for (int t = tq*8; t < tq*8 + 8; t++) {
            float a0 = b, a1 = 0.f, a2 = 0.f, a3 = 0.f;
            #pragma unroll
            for (int c = 0; c < 2*HLc; c += 4) {
                a0 = fmaf(hbuf[t][c+0], wr[c+0], a0);
                a1 = fmaf(hbuf[t][c+1], wr[c+1], a1);
                a2 = fmaf(hbuf[t][c+2], wr[c+2], a2);
                a3 = fmaf(hbuf[t][c+3], wr[c+3], a3);
            }
            pre[t][gate] = (a0 + a1) + (a2 + a3);
        }
    }
    __syncthreads();

    if (tid < 64) {
        const int dir = tid >> 5, u = tid & 31;
        float wi[HLc], wf[HLc], wg[HLc], wo[HLc];
        if (u < HLc) {
            #pragma unroll
            for (int c = 0; c < HLc; c++) {
                wi[c] = wh1sh[(dir*G4      + u)*HLc + c];
                wf[c] = wh1sh[(dir*G4 + 12 + u)*HLc + c];
                wg[c] = wh1sh[(dir*G4 + 24 + u)*HLc + c];
                wo[c] = wh1sh[(dir*G4 + 36 + u)*HLc + c];
            }
        } else {
            #pragma unroll
            for (int c = 0; c < HLc; c++) { wi[c]=wf[c]=wg[c]=wo[c]=0.f; }
        }
        float h = 0.f, cs = 0.f;
        for (int s = 0; s < TT; s++) {
            const int t = dir ? (TT - 1 - s) : s;
            float gi, gf, gg, go;
            if (u < HLc) {
                gi = pre[t][dir*G4      + u];
                gf = pre[t][dir*G4 + 12 + u];
                gg = pre[t][dir*G4 + 24 + u];
                go = pre[t][dir*G4 + 36 + u];
            } else { gi = gf = gg = go = 0.f; }
            #pragma unroll
            for (int c = 0; c < HLc; c++) {
                float hc = __shfl_sync(0xffffffffu, h, c);
                gi = fmaf(hc, wi[c], gi);
                gf = fmaf(hc, wf[c], gf);
                gg = fmaf(hc, wg[c], gg);
                go = fmaf(hc, wo[c], go);
            }
            cs = sigf(gf)*cs + sigf(gi)*tanh_fast(gg);
            h  = sigf(go)*tanh_fast(cs);
            if (u < HLc) hbuf[t][dir*HLc + u] = h;
        }
    }
    __syncthreads();

    if (tid < 576) {
        const int oc = tid % 72;
        const int tq = tid / 72;
        float wr[NUc];
        #pragma unroll
        for (int c = 0; c < NUc; c++) wr[c] = wqsh[oc*NUc + c];
        const float b = bqsh[oc];
        const int e  = oc / NUc;
        const int ch = oc % NUc;
        const float scale = (e == 0) ? QSCALE : 1.0f;
        float* dst = (e == 0) ? g_q0 : (e == 1) ? g_k0 : g_v0;
        for (int t = tq*8; t < tq*8 + 8; t++) {
            float a0 = b, a1 = 0.f, a2 = 0.f, a3 = 0.f;
            #pragma unroll
            for (int c = 0; c < NUc; c += 4) {
                a0 = fmaf(hbuf[t][c+0], wr[c+0], a0);
                a1 = fmaf(hbuf[t][c+1], wr[c+1], a1);
                a2 = fmaf(hbuf[t][c+2], wr[c+2], a2);
                a3 = fmaf(hbuf[t][c+3], wr[c+3], a3);
            }
            dst[(t*WW + w)*NUc + ch] = ((a0 + a1) + (a2 + a3)) * scale;
        }
    }
}

// ---------------------------------------------------------------------------
// NATTEN-2D: 4x8 tile, 512 threads = 16 warps = (head, row), 2 chunks of 4
// queries per warp (R15 structure) + polynomial exp on the FMA pipe.
// ---------------------------------------------------------------------------
__global__ void __launch_bounds__(512)
natten_kernel(const float* __restrict__ qsrc,
              const float* __restrict__ ksrc,
              const float* __restrict__ vsrc,
              const float* __restrict__ rpb,
              const float* __restrict__ pw,
              const float* __restrict__ pb,
              const float* __restrict__ qkv_w,
              const float* __restrict__ qkv_b,
              const float* __restrict__ ow,
              const float* __restrict__ ob,
              float* __restrict__ out,
              int mode)
{
    const int i0 = blockIdx.y * 4;
    const int j0 = blockIdx.x * 8;
    extern __shared__ float sm[];
    float* ks   = sm;                           // [28*32][PITCH]
    float* vs   = ks + UROWS*32*PITCH;
    float* rpsh = vs + UROWS*32*PITCH;          // [4][28][49]
    float* ao   = rpsh + 4*RPROWS*49;           // [32][24]
    float* po   = ao + 32*NUc;                  // [32][24]
    float* wsh  = po + 32*NUc;                  // [72*24]
    float* bsh  = wsh + 72*NUc;                 // [72]

    const int tid = threadIdx.x;

    const int si0 = min(max(i0     - 12, 0), TT - KK);
    const int si3 = min(max(i0 + 3 - 12, 0), TT - KK);
    const int nrows = si3 + KK - si0;                      // 25..28
    const int sj_min  = min(max(j0     - 12, 0), WW - KK);
    const int sj_last = min(max(j0 + 7 - 12, 0), WW - KK);
    const int ncols   = sj_last + KK - sj_min;             // <= 32
    const int rmin = si3 - (i0 + 3) + (KK - 1);

    if (mode == 0) {
        for (int x = tid; x < 72*NUc; x += 512) wsh[x] = qkv_w[x];
        if (tid < 72) bsh[tid] = qkv_b[tid];
    }

    for (int idx = tid; idx < 4*RPROWS*49; idx += 512) {
        int hn = idx / (RPROWS*49);
        int rem = idx - hn*(RPROWS*49);
        int rr = rem / 49, cc = rem - rr*49;
        rpsh[idx] = __ldg(rpb + hn*2401 + (rmin + rr)*49 + cc);
    }

    const int npx = nrows * 32;
    for (int spx = tid; spx < npx; spx += 512) {
        int a = spx >> 5, c = spx & 31;
        int cc = min(c, ncols - 1);
        int gpx = (si0 + a)*WW + (sj_min + cc);
        float* kdst = ks + (a*32 + c)*PITCH;
        float* vdst = vs + (a*32 + c)*PITCH;
        const float4* kp = (const float4*)(ksrc + gpx*NUc);
        const float4* vp = (const float4*)(vsrc + gpx*NUc);
        #pragma unroll
        for (int f = 0; f < 6; f++) {
            float4 kd = kp[f];
            *(float2*)(kdst + f*4)     = make_float2(kd.x, kd.y);
            *(float2*)(kdst + f*4 + 2) = make_float2(kd.z, kd.w);
        }
        #pragma unroll
        for (int f = 0; f < 6; f++) {
            float4 vd = vp[f];
            *(float2*)(vdst + f*4)     = make_float2(vd.x, vd.y);
            *(float2*)(vdst + f*4 + 2) = make_float2(vd.z, vd.w);
        }
    }
    __syncthreads();

    const int warp = tid >> 5, lane = tid & 31;
    const int n = warp & 3;             // head
    const int r = warp >> 2;            // row 0..3

    const int i = i0 + r;
    const int sir = min(max(i - 12, 0), TT - KK);
    const int arow = sir - si0;
    const int ra   = (sir - i + (KK - 1)) - rmin;
    const float* rpw = rpsh + n*(RPROWS*49) + ra*49;

    for (int chk = 0; chk < 2; chk++) {
        const int p0 = chk*4;

        int   rjp[4];
        float vf [4];
        #pragma unroll
        for (int q = 0; q < 4; q++) {
            int p = p0 + q;
            int sj = min(max(j0 + p - 12, 0), WW - KK);
            int cb = sj - sj_min;
            bool valid = ((unsigned)(lane - cb)) < 25u;
            int rj = (lane - cb) + (sj - (j0 + p) + (KK - 1));
            rjp[q] = min(max(rj, 0), 48);
            vf[q]  = valid ? 1.0f : 0.0f;
        }

        float qv[24];
        #pragma unroll
        for (int q = 0; q < 4; q++) {
            const float2* qp = (const float2*)(qsrc + ((i*WW + j0 + p0 + q)*NUc + n*HDd));
            float2 a0 = qp[0], a1 = qp[1], a2 = qp[2];
            qv[q*6+0]=a0.x; qv[q*6+1]=a0.y;
            qv[q*6+2]=a1.x; qv[q*6+3]=a1.y;
            qv[q*6+4]=a2.x; qv[q*6+5]=a2.y;
        }

        float sum[4];
        float oa[24];
        #pragma unroll
        for (int q = 0; q < 4; q++) sum[q] = 0.f;
        #pragma unroll
        for (int x = 0; x < 24; x++) oa[x] = 0.f;

        #pragma unroll 1
        for (int a = 0; a < KK; a++) {
            const int base = ((arow + a)*32 + lane)*PITCH + n*HDd;
            const float* kp = ks + base;
            const float* vp = vs + base;
            float2 k01 = *(const float2*)(kp);
            float2 k23 = *(const float2*)(kp + 2);
            float2 k45 = *(const float2*)(kp + 4);
            float2 v01 = *(const float2*)(vp);
            float2 v23 = *(const float2*)(vp + 2);
            float2 v45 = *(const float2*)(vp + 4);
            const float* rpr = rpw + a*49;
            #pragma unroll
            for (int q = 0; q < 4; q++) {
                float lg = rpr[rjp[q]];
                lg = fmaf(qv[q*6+0], k01.x, lg);
                lg = fmaf(qv[q*6+1], k01.y, lg);
                lg = fmaf(qv[q*6+2], k23.x, lg);
                lg = fmaf(qv[q*6+3], k23.y, lg);
                lg = fmaf(qv[q*6+4], k45.x, lg);
                lg = fmaf(qv[q*6+5], k45.y, lg);
                float pr = exp_fma(lg) * vf[q];
                sum[q] += pr;
                oa[q*6+0] = fmaf(pr, v01.x, oa[q*6+0]);
                oa[q*6+1] = fmaf(pr, v01.y, oa[q*6+1]);
                oa[q*6+2] = fmaf(pr, v23.x, oa[q*6+2]);
                oa[q*6+3] = fmaf(pr, v23.y, oa[q*6+3]);
                oa[q*6+4] = fmaf(pr, v45.x, oa[q*6+4]);
                oa[q*6+5] = fmaf(pr, v45.y, oa[q*6+5]);
            }
        }

        #pragma unroll
        for (int q = 0; q < 4; q++) {
            float s  = sum[q];
            float o0 = oa[q*6+0], o1 = oa[q*6+1], o2 = oa[q*6+2];
            float o3 = oa[q*6+3], o4 = oa[q*6+4], o5 = oa[q*6+5];
            #pragma unroll
            for (int off = 16; off > 0; off >>= 1) {
                s  += __shfl_xor_sync(0xffffffffu, s,  off);
                o0 += __shfl_xor_sync(0xffffffffu, o0, off);
                o1 += __shfl_xor_sync(0xffffffffu, o1, off);
                o2 += __shfl_xor_sync(0xffffffffu, o2, off);
                o3 += __shfl_xor_sync(0xffffffffu, o3, off);
                o4 += __shfl_xor_sync(0xffffffffu, o4, off);
                o5 += __shfl_xor_sync(0xffffffffu, o5, off);
            }
            if (lane == 0) {
                float inv = 1.0f / s;
                float* dst = ao + (r*8 + p0 + q)*NUc + n*HDd;
                dst[0]=o0*inv; dst[1]=o1*inv; dst[2]=o2*inv;
                dst[3]=o3*inv; dst[4]=o4*inv; dst[5]=o5*inv;
            }
        }
    }
    __syncthreads();

    // output projection (24x24) for 32 pixels
    for (int idx = tid; idx < 32*NUc; idx += 512) {
        int pp = idx / NUc, oc = idx % NUc;
        float acc = __ldg(pb + oc);
        const float* wrow = pw + oc*NUc;
        #pragma unroll
        for (int ic = 0; ic < NUc; ic++)
            acc = fmaf(ao[pp*NUc + ic], __ldg(wrow + ic), acc);
        po[pp*NUc + oc] = acc;
    }
    __syncthreads();

    if (mode == 0) {
        for (int idx = tid; idx < 32*72; idx += 512) {
            int pp = idx / 72, oc = idx % 72;
            float acc = bsh[oc];
            const float* wrow = wsh + oc*NUc;
            const float* xr = po + pp*NUc;
            #pragma unroll
            for (int c = 0; c < NUc; c++) acc = fmaf(xr[c], wrow[c], acc);
            int e = oc / NUc, ch = oc % NUc;
            int gpx = (i0 + (pp >> 3))*WW + j0 + (pp & 7);
            if      (e == 0) g_q1[gpx*NUc + ch] = acc * QSCALE;
            else if (e == 1) g_k1[gpx*NUc + ch] = acc;
            else             g_v1[gpx*NUc + ch] = acc;
        }
    } else {
        if (tid < 32*5) {
            int pp = tid / 5, rr = tid % 5;
            float acc = __ldg(ob + rr);
            const float* wrow = ow + rr*NUc;
            #pragma unroll
            for (int ic = 0; ic < NUc; ic++)
                acc = fmaf(po[pp*NUc + ic], __ldg(wrow + ic), acc);
            out[((i0 + (pp >> 3))*WW + j0 + (pp & 7))*5 + rr] = acc;
        }
    }
}

// ---------------------------------------------------------------------------
extern "C" void kernel_launch(void* const* d_in, const int* in_sizes, int n_in,
                              void* d_out, int out_size)
{
    const float* features  = (const float*)d_in[0];
    const int*   condition = (const int*)  d_in[1];
    const float* mask      = (const float*)d_in[2];
    const float* emb       = (const float*)d_in[3];
    const float* wih0      = (const float*)d_in[4];
    const float* whh0      = (const float*)d_in[5];
    const float* bih0      = (const float*)d_in[6];
    const float* bhh0      = (const float*)d_in[7];
    const float* wih1      = (const float*)d_in[8];
    const float* whh1      = (const float*)d_in[9];
    const float* bih1      = (const float*)d_in[10];
    const float* bhh1      = (const float*)d_in[11];
    const float* qkv_w     = (const float*)d_in[12];
    const float* qkv_b     = (const float*)d_in[13];
    const float* rpb       = (const float*)d_in[14];
    const float* proj_w    = (const float*)d_in[15];
    const float* proj_b    = (const float*)d_in[16];
    const float* out_w     = (const float*)d_in[17];
    const float* out_b     = (const float*)d_in[18];
    float* out = (float*)d_out;

    float *pq0, *pk0, *pv0, *pq1, *pk1, *pv1;
    cudaGetSymbolAddress((void**)&pq0, g_q0);
    cudaGetSymbolAddress((void**)&pk0, g_k0);
    cudaGetSymbolAddress((void**)&pv0, g_v0);
    cudaGetSymbolAddress((void**)&pq1, g_q1);
    cudaGetSymbolAddress((void**)&pk1, g_k1);
    cudaGetSymbolAddress((void**)&pv1, g_v1);

    const int natten_smem =
        (2*UROWS*32*PITCH + 4*RPROWS*49 + 2*32*NUc + 72*NUc + 72)
        * (int)sizeof(float);
    cudaFuncSetAttribute(natten_kernel,
                         cudaFuncAttributeMaxDynamicSharedMemorySize, natten_smem);

    // 1) fused LSTM + QKV(layer1)
    lstm_kernel<<<WW, 768>>>(features, condition, mask, emb,
                             wih0, whh0, bih0, bhh0,
                             wih1, whh1, bih1, bhh1,
                             qkv_w, qkv_b);

    dim3 ngrid(WW/8, TT/4);   // 11 x 16 = 176 blocks

    // 2) NATTEN layer 1 (+ fused QKV for layer 2)
    natten_kernel<<<ngrid, 512, natten_smem>>>(pq0, pk0, pv0,
                                               rpb, proj_w, proj_b,
                                               qkv_w, qkv_b, out_w, out_b,
                                               nullptr, 0);

    // 3) NATTEN layer 2 (+ fused head) -> d_out
    natten_kernel<<<ngrid, 512, natten_smem>>>(pq1, pk1, pv1,
                                               rpb, proj_w, proj_b,
                                               qkv_w, qkv_b, out_w, out_b,
                                               out, 1);
}

// round 17
// speedup vs baseline: 1.3520x; 1.3520x over previous
#include <cuda_runtime.h>
#include <cuda_bf16.h>

// Problem constants
#define TT   64
#define WW   88
#define HPc  48
#define CIN  53
#define HLc  12
#define G4   48
#define NHh  4
#define HDd  6
#define NUc  24
#define KK   25
#define NPX  (TT*WW)   // 5632
#define PITCH 26
#define TROWS 5        // natten tile rows
#define UROWS 29       // max union rows (5 + 24)
#define RPROWS 29

// Scratch buffers (device globals)
__device__ float g_q0[NPX*NUc];
__device__ float g_k0[NPX*NUc];
__device__ float g_v0[NPX*NUc];
__device__ float g_q1[NPX*NUc];
__device__ float g_k1[NPX*NUc];
__device__ float g_v1[NPX*NUc];

#define QSCALE 0.4082482904638631f

__device__ __forceinline__ float sigf(float x) {
    return __fdividef(1.0f, 1.0f + __expf(-x));
}
__device__ __forceinline__ float tanh_fast(float x) {
    return fmaf(2.0f, __fdividef(1.0f, 1.0f + __expf(-2.0f*x)), -1.0f);
}

// ---------------------------------------------------------------------------
// Fused LSTM + QKV(layer1). Block per sequence (w), 768 threads. (R15 exact)
// ---------------------------------------------------------------------------
__global__ void __launch_bounds__(768)
lstm_kernel(const float* __restrict__ features,
            const int*   __restrict__ condition,
            const float* __restrict__ mask,
            const float* __restrict__ emb,
            const float* __restrict__ wih0, const float* __restrict__ whh0,
            const float* __restrict__ bih0, const float* __restrict__ bhh0,
            const float* __restrict__ wih1, const float* __restrict__ whh1,
            const float* __restrict__ bih1, const float* __restrict__ bhh1,
            const float* __restrict__ qkv_w,
            const float* __restrict__ qkv_b)
{
    const int w   = blockIdx.x;
    const int tid = threadIdx.x;

    __shared__ float xs  [TT][CIN];
    __shared__ float pre [TT][96];
    __shared__ float hbuf[TT][2*HLc];
    __shared__ float w0sh [96*CIN];
    __shared__ float wh0sh[96*HLc];
    __shared__ float w1sh [96*2*HLc];
    __shared__ float wh1sh[96*HLc];
    __shared__ float wqsh [72*NUc];
    __shared__ float b0sh[96], b1sh[96], bqsh[72];

    for (int idx = tid; idx < TT*CIN; idx += 768) {
        int t = idx / CIN, c = idx % CIN;
        float val;
        if (c < HPc)            val = features[(t*HPc + c)*WW + w];
        else if (c < HPc + 4)   val = emb[condition[t*WW + w]*4 + (c - HPc)];
        else                    val = mask[t*WW + w];
        xs[t][c] = val;
    }
    for (int x = tid; x < 96*CIN/4;   x += 768)
        ((float4*)w0sh)[x]  = ((const float4*)wih0)[x];
    for (int x = tid; x < 96*HLc/4;   x += 768)
        ((float4*)wh0sh)[x] = ((const float4*)whh0)[x];
    for (int x = tid; x < 96*2*HLc/4; x += 768)
        ((float4*)w1sh)[x]  = ((const float4*)wih1)[x];
    for (int x = tid; x < 96*HLc/4;   x += 768)
        ((float4*)wh1sh)[x] = ((const float4*)whh1)[x];
    for (int x = tid; x < 72*NUc/4;   x += 768)
        ((float4*)wqsh)[x]  = ((const float4*)qkv_w)[x];
    if (tid < 96) b0sh[tid] = bih0[tid] + bhh0[tid];
    if (tid < 96) b1sh[tid] = bih1[tid] + bhh1[tid];
    if (tid < 72) bqsh[tid] = qkv_b[tid];
    __syncthreads();

    {
        const int gate = tid % 96;
        const int tq   = tid / 96;
        float wr[CIN];
        #pragma unroll
        for (int c = 0; c < CIN; c++) wr[c] = w0sh[gate*CIN + c];
        const float b = b0sh[gate];
        for (int t = tq*8; t < tq*8 + 8; t++) {
            float a0 = b, a1 = 0.f, a2 = 0.f, a3 = 0.f;
            #pragma unroll
            for (int c = 0; c < 52; c += 4) {
                a0 = fmaf(xs[t][c+0], wr[c+0], a0);
                a1 = fmaf(xs[t][c+1], wr[c+1], a1);
                a2 = fmaf(xs[t][c+2], wr[c+2], a2);
                a3 = fmaf(xs[t][c+3], wr[c+3], a3);
            }
            a0 = fmaf(xs[t][52], wr[52], a0);
            pre[t][gate] = (a0 + a1) + (a2 + a3);
        }
    }
    __syncthreads();

    if (tid < 64) {
        const int dir = tid >> 5, u = tid & 31;
        float wi[HLc], wf[HLc], wg[HLc], wo[HLc];
        if (u < HLc) {
            #pragma unroll
            for (int c = 0; c < HLc; c++) {
                wi[c] = wh0sh[(dir*G4      + u)*HLc + c];
                wf[c] = wh0sh[(dir*G4 + 12 + u)*HLc + c];
                wg[c] = wh0sh[(dir*G4 + 24 + u)*HLc + c];
                wo[c] = wh0sh[(dir*G4 + 36 + u)*HLc + c];
            }
        } else {
            #pragma unroll
            for (int c = 0; c < HLc; c++) { wi[c]=wf[c]=wg[c]=wo[c]=0.f; }
        }
        float h = 0.f, cs = 0.f;
        for (int s = 0; s < TT; s++) {
            const int t = dir ? (TT - 1 - s) : s;
            float gi, gf, gg, go;
            if (u < HLc) {
                gi = pre[t][dir*G4      + u];
                gf = pre[t][dir*G4 + 12 + u];
                gg = pre[t][dir*G4 + 24 + u];
                go = pre[t][dir*G4 + 36 + u];
            } else { gi = gf = gg = go = 0.f; }
            #pragma unroll
            for (int c = 0; c < HLc; c++) {
                float hc = __shfl_sync(0xffffffffu, h, c);
                gi = fmaf(hc, wi[c], gi);
                gf = fmaf(hc, wf[c], gf);
                gg = fmaf(hc, wg[c], gg);
                go = fmaf(hc, wo[c], go);
            }
            cs = sigf(gf)*cs + sigf(gi)*tanh_fast(gg);
            h  = sigf(go)*tanh_fast(cs);
            if (u < HLc) hbuf[t][dir*HLc + u] = h;
        }
    }
    __syncthreads();

    {
        const int gate = tid % 96;
        const int tq   = tid / 96;
        float wr[2*HLc];
        #pragma unroll
        for (int c = 0; c < 2*HLc; c++) wr[c] = w1sh[gate*2*HLc + c];
        const float b = b1sh[gate];
        for (int t = tq*8; t < tq*8 + 8; t++) {
            float a0 = b, a1 = 0.f, a2 = 0.f, a3 = 0.f;
            #pragma unroll
            for (int c = 0; c < 2*HLc; c += 4) {
                a0 = fmaf(hbuf[t][c+0], wr[c+0], a0);
                a1 = fmaf(hbuf[t][c+1], wr[c+1], a1);
                a2 = fmaf(hbuf[t][c+2], wr[c+2], a2);
                a3 = fmaf(hbuf[t][c+3], wr[c+3], a3);
            }
            pre[t][gate] = (a0 + a1) + (a2 + a3);
        }
    }
    __syncthreads();

    if (tid < 64) {
        const int dir = tid >> 5, u = tid & 31;
        float wi[HLc], wf[HLc], wg[HLc], wo[HLc];
        if (u < HLc) {
            #pragma unroll
            for (int c = 0; c < HLc; c++) {
                wi[c] = wh1sh[(dir*G4      + u)*HLc + c];
                wf[c] = wh1sh[(dir*G4 + 12 + u)*HLc + c];
                wg[c] = wh1sh[(dir*G4 + 24 + u)*HLc + c];
                wo[c] = wh1sh[(dir*G4 + 36 + u)*HLc + c];
            }
        } else {
            #pragma unroll
            for (int c = 0; c < HLc; c++) { wi[c]=wf[c]=wg[c]=wo[c]=0.f; }
        }
        float h = 0.f, cs = 0.f;
        for (int s = 0; s < TT; s++) {
            const int t = dir ? (TT - 1 - s) : s;
            float gi, gf, gg, go;
            if (u < HLc) {
                gi = pre[t][dir*G4      + u];
                gf = pre[t][dir*G4 + 12 + u];
                gg = pre[t][dir*G4 + 24 + u];
                go = pre[t][dir*G4 + 36 + u];
            } else { gi = gf = gg = go = 0.f; }
            #pragma unroll
            for (int c = 0; c < HLc; c++) {
                float hc = __shfl_sync(0xffffffffu, h, c);
                gi = fmaf(hc, wi[c], gi);
                gf = fmaf(hc, wf[c], gf);
                gg = fmaf(hc, wg[c], gg);
                go = fmaf(hc, wo[c], go);
            }
            cs = sigf(gf)*cs + sigf(gi)*tanh_fast(gg);
            h  = sigf(go)*tanh_fast(cs);
            if (u < HLc) hbuf[t][dir*HLc + u] = h;
        }
    }
    __syncthreads();

    if (tid < 576) {
        const int oc = tid % 72;
        const int tq = tid / 72;
        float wr[NUc];
        #pragma unroll
        for (int c = 0; c < NUc; c++) wr[c] = wqsh[oc*NUc + c];
        const float b = bqsh[oc];
        const int e  = oc / NUc;
        const int ch = oc % NUc;
        const float scale = (e == 0) ? QSCALE : 1.0f;
        float* dst = (e == 0) ? g_q0 : (e == 1) ? g_k0 : g_v0;
        for (int t = tq*8; t < tq*8 + 8; t++) {
            float a0 = b, a1 = 0.f, a2 = 0.f, a3 = 0.f;
            #pragma unroll
            for (int c = 0; c < NUc; c += 4) {
                a0 = fmaf(hbuf[t][c+0], wr[c+0], a0);
                a1 = fmaf(hbuf[t][c+1], wr[c+1], a1);
                a2 = fmaf(hbuf[t][c+2], wr[c+2], a2);
                a3 = fmaf(hbuf[t][c+3], wr[c+3], a3);
            }
            dst[(t*WW + w)*NUc + ch] = ((a0 + a1) + (a2 + a3)) * scale;
        }
    }
}

// ---------------------------------------------------------------------------
// NATTEN-2D: 5x8 tile, 640 threads = 20 warps = (head, row 0..4).
// Grid 11 x 13 = 143 blocks <= 148 SMs -> ONE wave (kills wave quantization).
// Per warp: 8 queries as 2 chunks of 4 (spill-safe at 102-reg cap).
// ---------------------------------------------------------------------------
__global__ void __launch_bounds__(640)
natten_kernel(const float* __restrict__ qsrc,
              const float* __restrict__ ksrc,
              const float* __restrict__ vsrc,
              const float* __restrict__ rpb,
              const float* __restrict__ pw,
              const float* __restrict__ pb,
              const float* __restrict__ qkv_w,
              const float* __restrict__ qkv_b,
              const float* __restrict__ ow,
              const float* __restrict__ ob,
              float* __restrict__ out,
              int mode)
{
    const int i0 = blockIdx.y * TROWS;
    const int j0 = blockIdx.x * 8;
    const int nr = min(TROWS, TT - i0);          // 5, or 4 for last tile
    extern __shared__ float sm[];
    float* ks   = sm;                            // [29*32][PITCH]
    float* vs   = ks + UROWS*32*PITCH;
    float* rpsh = vs + UROWS*32*PITCH;           // [4][29][49]
    float* ao   = rpsh + 4*RPROWS*49;            // [40][24]
    float* po   = ao + TROWS*8*NUc;              // [40][24]

    const int tid = threadIdx.x;

    const int si0 = min(max(i0          - 12, 0), TT - KK);
    const int siL = min(max(i0 + nr - 1 - 12, 0), TT - KK);
    const int nrows = siL + KK - si0;                      // <= 29
    const int sj_min  = min(max(j0     - 12, 0), WW - KK);
    const int sj_last = min(max(j0 + 7 - 12, 0), WW - KK);
    const int ncols   = sj_last + KK - sj_min;             // <= 32
    const int rmin = siL - (i0 + nr - 1) + (KK - 1);

    // stage rpb (rows rmin..rmin+28 always within [0,48] by construction;
    // clamp row index defensively)
    for (int idx = tid; idx < 4*RPROWS*49; idx += 640) {
        int hn = idx / (RPROWS*49);
        int rem = idx - hn*(RPROWS*49);
        int rr = rem / 49, cc = rem - rr*49;
        int rrow = min(rmin + rr, 48);
        rpsh[idx] = __ldg(rpb + hn*2401 + rrow*49 + cc);
    }

    const int npx = nrows * 32;
    for (int spx = tid; spx < npx; spx += 640) {
        int a = spx >> 5, c = spx & 31;
        int cc = min(c, ncols - 1);
        int gpx = (si0 + a)*WW + (sj_min + cc);
        float* kdst = ks + (a*32 + c)*PITCH;
        float* vdst = vs + (a*32 + c)*PITCH;
        const float4* kp = (const float4*)(ksrc + gpx*NUc);
        const float4* vp = (const float4*)(vsrc + gpx*NUc);
        #pragma unroll
        for (int f = 0; f < 6; f++) {
            float4 kd = kp[f];
            *(float2*)(kdst + f*4)     = make_float2(kd.x, kd.y);
            *(float2*)(kdst + f*4 + 2) = make_float2(kd.z, kd.w);
        }
        #pragma unroll
        for (int f = 0; f < 6; f++) {
            float4 vd = vp[f];
            *(float2*)(vdst + f*4)     = make_float2(vd.x, vd.y);
            *(float2*)(vdst + f*4 + 2) = make_float2(vd.z, vd.w);
        }
    }
    __syncthreads();

    const int warp = tid >> 5, lane = tid & 31;
    const int n = warp & 3;             // head
    const int r = warp >> 2;            // row 0..4

    if (r < nr) {
        const int i = i0 + r;
        const int sir = min(max(i - 12, 0), TT - KK);
        const int arow = sir - si0;
        const int ra   = (sir - i + (KK - 1)) - rmin;
        const float* rpw = rpsh + n*(RPROWS*49) + ra*49;

        for (int chk = 0; chk < 2; chk++) {
            const int p0 = chk*4;

            int   rjp[4];
            float vf [4];
            #pragma unroll
            for (int q = 0; q < 4; q++) {
                int p = p0 + q;
                int sj = min(max(j0 + p - 12, 0), WW - KK);
                int cb = sj - sj_min;
                bool valid = ((unsigned)(lane - cb)) < 25u;
                int rj = (lane - cb) + (sj - (j0 + p) + (KK - 1));
                rjp[q] = min(max(rj, 0), 48);
                vf[q]  = valid ? 1.0f : 0.0f;
            }

            float qv[24];
            #pragma unroll
            for (int q = 0; q < 4; q++) {
                const float2* qp = (const float2*)(qsrc + ((i*WW + j0 + p0 + q)*NUc + n*HDd));
                float2 a0 = qp[0], a1 = qp[1], a2 = qp[2];
                qv[q*6+0]=a0.x; qv[q*6+1]=a0.y;
                qv[q*6+2]=a1.x; qv[q*6+3]=a1.y;
                qv[q*6+4]=a2.x; qv[q*6+5]=a2.y;
            }

            float sum[4];
            float oa[24];
            #pragma unroll
            for (int q = 0; q < 4; q++) sum[q] = 0.f;
            #pragma unroll
            for (int x = 0; x < 24; x++) oa[x] = 0.f;

            #pragma unroll 1
            for (int a = 0; a < KK; a++) {
                const int base = ((arow + a)*32 + lane)*PITCH + n*HDd;
                const float* kp = ks + base;
                const float* vp = vs + base;
                float2 k01 = *(const float2*)(kp);
                float2 k23 = *(const float2*)(kp + 2);
                float2 k45 = *(const float2*)(kp + 4);
                float2 v01 = *(const float2*)(vp);
                float2 v23 = *(const float2*)(vp + 2);
                float2 v45 = *(const float2*)(vp + 4);
                const float* rpr = rpw + a*49;
                #pragma unroll
                for (int q = 0; q < 4; q++) {
                    float lg = rpr[rjp[q]];
                    lg = fmaf(qv[q*6+0], k01.x, lg);
                    lg = fmaf(qv[q*6+1], k01.y, lg);
                    lg = fmaf(qv[q*6+2], k23.x, lg);
                    lg = fmaf(qv[q*6+3], k23.y, lg);
                    lg = fmaf(qv[q*6+4], k45.x, lg);
                    lg = fmaf(qv[q*6+5], k45.y, lg);
                    float pr = __expf(lg) * vf[q];
                    sum[q] += pr;
                    oa[q*6+0] = fmaf(pr, v01.x, oa[q*6+0]);
                    oa[q*6+1] = fmaf(pr, v01.y, oa[q*6+1]);
                    oa[q*6+2] = fmaf(pr, v23.x, oa[q*6+2]);
                    oa[q*6+3] = fmaf(pr, v23.y, oa[q*6+3]);
                    oa[q*6+4] = fmaf(pr, v45.x, oa[q*6+4]);
                    oa[q*6+5] = fmaf(pr, v45.y, oa[q*6+5]);
                }
            }

            #pragma unroll
            for (int q = 0; q < 4; q++) {
                float s  = sum[q];
                float o0 = oa[q*6+0], o1 = oa[q*6+1], o2 = oa[q*6+2];
                float o3 = oa[q*6+3], o4 = oa[q*6+4], o5 = oa[q*6+5];
                #pragma unroll
                for (int off = 16; off > 0; off >>= 1) {
                    s  += __shfl_xor_sync(0xffffffffu, s,  off);
                    o0 += __shfl_xor_sync(0xffffffffu, o0, off);
                    o1 += __shfl_xor_sync(0xffffffffu, o1, off);
                    o2 += __shfl_xor_sync(0xffffffffu, o2, off);
                    o3 += __shfl_xor_sync(0xffffffffu, o3, off);
                    o4 += __shfl_xor_sync(0xffffffffu, o4, off);
                    o5 += __shfl_xor_sync(0xffffffffu, o5, off);
                }
                if (lane == 0) {
                    float inv = 1.0f / s;
                    float* dst = ao + (r*8 + p0 + q)*NUc + n*HDd;
                    dst[0]=o0*inv; dst[1]=o1*inv; dst[2]=o2*inv;
                    dst[3]=o3*inv; dst[4]=o4*inv; dst[5]=o5*inv;
                }
            }
        }
    }
    __syncthreads();

    const int npix = nr*8;

    // output projection (24x24)
    for (int idx = tid; idx < npix*NUc; idx += 640) {
        int pp = idx / NUc, oc = idx % NUc;
        float acc = __ldg(pb + oc);
        const float* wrow = pw + oc*NUc;
        #pragma unroll
        for (int ic = 0; ic < NUc; ic++)
            acc = fmaf(ao[pp*NUc + ic], __ldg(wrow + ic), acc);
        po[pp*NUc + oc] = acc;
    }
    __syncthreads();

    if (mode == 0) {
        for (int idx = tid; idx < npix*72; idx += 640) {
            int pp = idx / 72, oc = idx % 72;
            float acc = __ldg(qkv_b + oc);
            const float* wrow = qkv_w + oc*NUc;
            const float* xr = po + pp*NUc;
            #pragma unroll
            for (int c = 0; c < NUc; c++)
                acc = fmaf(xr[c], __ldg(wrow + c), acc);
            int e = oc / NUc, ch = oc % NUc;
            int gpx = (i0 + (pp >> 3))*WW + j0 + (pp & 7);
            if      (e == 0) g_q1[gpx*NUc + ch] = acc * QSCALE;
            else if (e == 1) g_k1[gpx*NUc + ch] = acc;
            else             g_v1[gpx*NUc + ch] = acc;
        }
    } else {
        if (tid < npix*5) {
            int pp = tid / 5, rr = tid % 5;
            float acc = __ldg(ob + rr);
            const float* wrow = ow + rr*NUc;
            #pragma unroll
            for (int ic = 0; ic < NUc; ic++)
                acc = fmaf(po[pp*NUc + ic], __ldg(wrow + ic), acc);
            out[((i0 + (pp >> 3))*WW + j0 + (pp & 7))*5 + rr] = acc;
        }
    }
}

// ---------------------------------------------------------------------------
extern "C" void kernel_launch(void* const* d_in, const int* in_sizes, int n_in,
                              void* d_out, int out_size)
{
    const float* features  = (const float*)d_in[0];
    const int*   condition = (const int*)  d_in[1];
    const float* mask      = (const float*)d_in[2];
    const float* emb       = (const float*)d_in[3];
    const float* wih0      = (const float*)d_in[4];
    const float* whh0      = (const float*)d_in[5];
    const float* bih0      = (const float*)d_in[6];
    const float* bhh0      = (const float*)d_in[7];
    const float* wih1      = (const float*)d_in[8];
    const float* whh1      = (const float*)d_in[9];
    const float* bih1      = (const float*)d_in[10];
    const float* bhh1      = (const float*)d_in[11];
    const float* qkv_w     = (const float*)d_in[12];
    const float* qkv_b     = (const float*)d_in[13];
    const float* rpb       = (const float*)d_in[14];
    const float* proj_w    = (const float*)d_in[15];
    const float* proj_b    = (const float*)d_in[16];
    const float* out_w     = (const float*)d_in[17];
    const float* out_b     = (const float*)d_in[18];
    float* out = (float*)d_out;

    float *pq0, *pk0, *pv0, *pq1, *pk1, *pv1;
    cudaGetSymbolAddress((void**)&pq0, g_q0);
    cudaGetSymbolAddress((void**)&pk0, g_k0);
    cudaGetSymbolAddress((void**)&pv0, g_v0);
    cudaGetSymbolAddress((void**)&pq1, g_q1);
    cudaGetSymbolAddress((void**)&pk1, g_k1);
    cudaGetSymbolAddress((void**)&pv1, g_v1);

    const int natten_smem =
        (2*UROWS*32*PITCH + 4*RPROWS*49 + 2*TROWS*8*NUc)
        * (int)sizeof(float);   // ~223.4 KB
    cudaFuncSetAttribute(natten_kernel,
                         cudaFuncAttributeMaxDynamicSharedMemorySize, natten_smem);

    // 1) fused LSTM + QKV(layer1)
    lstm_kernel<<<WW, 768>>>(features, condition, mask, emb,
                             wih0, whh0, bih0, bhh0,
                             wih1, whh1, bih1, bhh1,
                             qkv_w, qkv_b);

    dim3 ngrid(WW/8, (TT + TROWS - 1)/TROWS);   // 11 x 13 = 143 blocks

    // 2) NATTEN layer 1 (+ fused QKV for layer 2)
    natten_kernel<<<ngrid, 640, natten_smem>>>(pq0, pk0, pv0,
                                               rpb, proj_w, proj_b,
                                               qkv_w, qkv_b, out_w, out_b,
                                               nullptr, 0);

    // 3) NATTEN layer 2 (+ fused head) -> d_out
    natten_kernel<<<ngrid, 640, natten_smem>>>(pq1, pk1, pv1,
                                               rpb, proj_w, proj_b,
                                               qkv_w, qkv_b, out_w, out_b,
                                               out, 1);
}